// round 15
// baseline (speedup 1.0000x reference)
#include <cuda_runtime.h>
#include <cuda_bf16.h>
#include <cstdint>

// Problem constants
#define B_   4
#define F_   16
#define NP_  196
#define DIM_ 512
#define H_   8
#define DH_  64
#define NTOT 3137            // 1 + F*NP
#define MROWS (B_ * NTOT)    // 12548
#define MPAD  12800          // covers 99*128 and 198*64
#define QKVC (3 * H_ * DH_)  // 1536
#define NK_  197             // cls + 196 local keys
#define KP   1536            // split-bf16 K' = 3*512

// ---------------------------------------------------------------------------
// Scratch (allocation-free: __device__ globals; zero-initialized)
// ---------------------------------------------------------------------------
__device__ float         g_qkv[(size_t)MROWS * QKVC];
__device__ __nv_bfloat16 g_A2x[(size_t)MPAD * KP];
__device__ __nv_bfloat16 g_A2att[(size_t)MPAD * KP];
__device__ __nv_bfloat16 g_B2qkv[(size_t)QKVC * KP];
__device__ __nv_bfloat16 g_B2out[(size_t)DIM_ * KP];

// ---------------------------------------------------------------------------
__device__ __forceinline__ uint32_t smem_to_u32(const void* p) {
    uint32_t a;
    asm("{ .reg .u64 t; cvta.to.shared.u64 t, %1; cvt.u32.u64 %0, t; }"
        : "=r"(a) : "l"(p));
    return a;
}

__device__ __forceinline__ void split_bf16(float v, __nv_bfloat16& h, __nv_bfloat16& l) {
    h = __float2bfloat16_rn(v);
    l = __float2bfloat16_rn(v - __bfloat162float(h));
}
__device__ __forceinline__ uint32_t pack2(__nv_bfloat16 a, __nv_bfloat16 b) {
    __nv_bfloat162 t = __halves2bfloat162(a, b);
    return *(uint32_t*)&t;
}

// packed f32x2 helpers (sm_100+)
__device__ __forceinline__ unsigned long long ffma2(unsigned long long a,
                                                    unsigned long long b,
                                                    unsigned long long c) {
    unsigned long long d;
    asm("fma.rn.f32x2 %0, %1, %2, %3;" : "=l"(d) : "l"(a), "l"(b), "l"(c));
    return d;
}
__device__ __forceinline__ unsigned long long packf2(float x, float y) {
    unsigned long long r;
    asm("mov.b64 %0, {%1, %2};" : "=l"(r) : "f"(x), "f"(y));
    return r;
}
__device__ __forceinline__ void unpackf2(unsigned long long r, float& x, float& y) {
    asm("mov.b64 {%0, %1}, %2;" : "=f"(x), "=f"(y) : "l"(r));
}

#define LDSM4(r, addr) \
    asm volatile("ldmatrix.sync.aligned.m8n8.x4.shared.b16 {%0,%1,%2,%3}, [%4];" \
                 : "=r"((r)[0]), "=r"((r)[1]), "=r"((r)[2]), "=r"((r)[3]) \
                 : "r"(addr))
#define CPA16(dst, src) \
    asm volatile("cp.async.cg.shared.global [%0], [%1], 16;" :: "r"(dst), "l"(src))

// ---------------------------------------------------------------------------
// HMMA GEMM: C[M,N] = A2[M,KP] . B2[N,KP]^T (+ bias).
// BK=64, 128B smem rows, seg^(row&7) swizzle -> conflict-free ldmatrix.
// MS = m16 subtiles per warp (2 -> 128x128 CTA, 1 -> 64x128),
// NSTG = stages, MINB = min blocks/SM. 8 warps 4(m)x2(n).
// ---------------------------------------------------------------------------
#define BK2 64
#define KIT2 (KP / BK2)            // 24

template <int MS, int NSTG, int MINB>
__global__ __launch_bounds__(256, MINB)
void gemm_mma(const __nv_bfloat16* __restrict__ A2,
              const __nv_bfloat16* __restrict__ B2,
              const float* __restrict__ bias,
              float* __restrict__ C, int M, int N) {
    constexpr int GBMt = MS * 64;
    constexpr int A_B  = GBMt * 128;
    constexpr int STG  = A_B + 128 * 128;
    extern __shared__ __align__(128) unsigned char smem[];

    const int tid  = threadIdx.x;
    const int wid  = tid >> 5;
    const int lane = tid & 31;
    const int wm = (wid & 3) * (MS * 16);
    const int wn = (wid >> 2) * 64;
    const int tm = blockIdx.y * GBMt;
    const int tn = blockIdx.x * 128;

    const uint32_t sbase = smem_to_u32(smem);

    const int row0 = tid >> 3;
    const int seg  = tid & 7;
    const __nv_bfloat16* gA0 = A2 + (size_t)(tm + row0) * KP + seg * 8;
    const __nv_bfloat16* gB0 = B2 + (size_t)(tn + row0) * KP + seg * 8;
    const uint32_t oA0 = row0 * 128 + ((seg ^ (row0 & 7)) * 16);
    const uint32_t oB0 = A_B + oA0;

    auto issue_stage = [&](int it) {
        if (it < KIT2) {
            int k0 = it * BK2;
            uint32_t bo = sbase + (it % NSTG) * STG;
#pragma unroll
            for (int t = 0; t < MS * 2; t++)
                CPA16(bo + oA0 + t * 4096, gA0 + (size_t)t * 32 * KP + k0);
#pragma unroll
            for (int t = 0; t < 4; t++)
                CPA16(bo + oB0 + t * 4096, gB0 + (size_t)t * 32 * KP + k0);
        }
        asm volatile("cp.async.commit_group;");
    };

    float acc[MS][8][4];
#pragma unroll
    for (int i = 0; i < MS; i++)
#pragma unroll
        for (int j = 0; j < 8; j++)
#pragma unroll
            for (int r = 0; r < 4; r++) acc[i][j][r] = 0.0f;

    const int rbase = lane & 15;
    const int kh = lane >> 4;

#pragma unroll
    for (int s = 0; s < NSTG - 1; s++) issue_stage(s);

    for (int it = 0; it < KIT2; ++it) {
        asm volatile("cp.async.wait_group %0;" :: "n"(NSTG - 2));
        __syncthreads();
        issue_stage(it + NSTG - 1);

        const uint32_t aB = sbase + (it % NSTG) * STG;
        const uint32_t bB = aB + A_B;

#pragma unroll
        for (int kk = 0; kk < 4; kk++) {
            const int segl = kk * 2 + kh;
            uint32_t a[MS][4];
#pragma unroll
            for (int i = 0; i < MS; i++) {
                int rA = wm + i * 16 + rbase;
                LDSM4(a[i], aB + rA * 128 + ((segl ^ (rA & 7)) * 16));
            }
            uint32_t b[4][4];
#pragma unroll
            for (int j2 = 0; j2 < 4; j2++) {
                int rB = wn + j2 * 16 + rbase;
                LDSM4(b[j2], bB + rB * 128 + ((segl ^ (rB & 7)) * 16));
            }
#pragma unroll
            for (int i = 0; i < MS; i++)
#pragma unroll
                for (int j = 0; j < 8; j++) {
                    uint32_t b0 = b[j >> 1][(j & 1)];
                    uint32_t b1 = b[j >> 1][(j & 1) + 2];
                    asm volatile(
                        "mma.sync.aligned.m16n8k16.row.col.f32.bf16.bf16.f32 "
                        "{%0,%1,%2,%3}, {%4,%5,%6,%7}, {%8,%9}, {%0,%1,%2,%3};"
                        : "+f"(acc[i][j][0]), "+f"(acc[i][j][1]),
                          "+f"(acc[i][j][2]), "+f"(acc[i][j][3])
                        : "r"(a[i][0]), "r"(a[i][1]), "r"(a[i][2]), "r"(a[i][3]),
                          "r"(b0), "r"(b1));
                }
        }
    }

#pragma unroll
    for (int i = 0; i < MS; i++) {
        int row0e = tm + wm + i * 16 + (lane >> 2);
#pragma unroll
        for (int half = 0; half < 2; half++) {
            int row = row0e + half * 8;
            if (row >= M) continue;
#pragma unroll
            for (int j = 0; j < 8; j++) {
                int col = tn + wn + j * 8 + (lane & 3) * 2;
                float2 v;
                v.x = acc[i][j][half * 2 + 0];
                v.y = acc[i][j][half * 2 + 1];
                if (bias) {
                    float2 bb = *(const float2*)(bias + col);
                    v.x += bb.x; v.y += bb.y;
                }
                *(float2*)(C + (size_t)row * N + col) = v;
            }
        }
    }
}

// ---------------------------------------------------------------------------
// conv_x: x fp32 [M,512] -> A2 split-bf16 [M,1536]  (hi | lo | hi)
// ---------------------------------------------------------------------------
__global__ __launch_bounds__(256)
void conv_x_kernel(const float* __restrict__ x, __nv_bfloat16* __restrict__ A2) {
    size_t i = (size_t)blockIdx.x * blockDim.x + threadIdx.x;
    if (i >= (size_t)MROWS * 128) return;
    size_t row = i >> 7;
    int c4 = (int)(i & 127);
    float4 v = *(const float4*)(x + row * 512 + c4 * 4);
    __nv_bfloat16 h0, h1, h2, h3, l0, l1, l2, l3;
    split_bf16(v.x, h0, l0); split_bf16(v.y, h1, l1);
    split_bf16(v.z, h2, l2); split_bf16(v.w, h3, l3);
    uint2 hp = make_uint2(pack2(h0, h1), pack2(h2, h3));
    uint2 lp = make_uint2(pack2(l0, l1), pack2(l2, l3));
    __nv_bfloat16* base = A2 + row * KP + c4 * 4;
    *(uint2*)(base)        = hp;
    *(uint2*)(base + 512)  = lp;
    *(uint2*)(base + 1024) = hp;
}

// ---------------------------------------------------------------------------
// convW: W fp32 [512,N] -> B2 split-bf16 [N,1536] (transposed, hi | hi | lo)
// ---------------------------------------------------------------------------
__global__ __launch_bounds__(1024)
void convW_kernel(const float* __restrict__ W, __nv_bfloat16* __restrict__ B2, int N) {
    __shared__ float t[32][33];
    int n0 = blockIdx.x * 32, k0 = blockIdx.y * 32;
    int tx = threadIdx.x, ty = threadIdx.y;
    t[ty][tx] = W[(size_t)(k0 + ty) * N + n0 + tx];
    __syncthreads();
    int n = n0 + ty, k = k0 + tx;
    float v = t[tx][ty];
    __nv_bfloat16 h, l;
    split_bf16(v, h, l);
    size_t base = (size_t)n * KP + k;
    B2[base]        = h;
    B2[base + 512]  = h;
    B2[base + 1024] = l;
}

// ---------------------------------------------------------------------------
// Merged attention, 800 threads/block (25 warps/SM vs old 8 -> latency hidden).
// Blocks [0,512): local attention, 4 LANES PER QUERY (lane group lg=tid&3 owns
// dims [lg*16, lg*16+16)); dot = partial + 2x shfl.bfly(width 4); ~60 regs.
// Blocks [512,544): cls attention (25-warp adaptation). Writes split-bf16.
// ---------------------------------------------------------------------------
#define ATT_T 800

__global__ __launch_bounds__(ATT_T, 1)
void attn_kernel(const float* __restrict__ qkv, __nv_bfloat16* __restrict__ A2) {
    extern __shared__ float sh[];
    const int tid = threadIdx.x;

    if (blockIdx.x < 512) {
        float* Ks = sh;                 // [197][64]
        float* Vs = sh + NK_ * DH_;     // [197][64]
        __shared__ int s_maxk2;

        const int blk = blockIdx.x;
        const int b = blk / (H_ * F_);
        const int rem = blk % (H_ * F_);
        const int h = rem / F_;
        const int fi = rem % F_;
        const int t0 = 1 + fi * NP_;

        const size_t bbase = (size_t)b * NTOT * QKVC;
        const int hoff = h * DH_;

        if (tid == 0) s_maxk2 = 0;
        for (int idx = tid; idx < NK_ * (DH_ / 4); idx += ATT_T) {
            int j = idx >> 4;
            int d4 = idx & 15;
            int tok = (j == 0) ? 0 : (t0 + j - 1);
            const float* kp = qkv + bbase + (size_t)tok * QKVC + DIM_ + hoff + d4 * 4;
            *(float4*)&Ks[j * DH_ + d4 * 4] = *(const float4*)kp;
            *(float4*)&Vs[j * DH_ + d4 * 4] = *(const float4*)(kp + DIM_);
        }
        __syncthreads();

        if (tid < NK_) {
            float kn2 = 0.0f;
#pragma unroll
            for (int i = 0; i < 16; i++) {
                float4 kk = *(const float4*)&Ks[tid * DH_ + i * 4];
                kn2 += kk.x * kk.x + kk.y * kk.y + kk.z * kk.z + kk.w * kk.w;
            }
            atomicMax(&s_maxk2, __float_as_int(kn2));
        }
        __syncthreads();
        const float maxk2 = __int_as_float(s_maxk2);

        const int qgrp = tid >> 2;              // 0..199
        const int lg   = tid & 3;               // dim slice
        const int qi   = (qgrp < NP_) ? qgrp : (NP_ - 1);   // clamp for uniform exec
        const int qtok = t0 + qi;
        const float scale = 0.125f;

        // lane's 16 q dims, packed f32x2
        const float* qp = qkv + bbase + (size_t)qtok * QKVC + hoff + lg * 16;
        unsigned long long q2[8];
        float qn2 = 0.0f;
#pragma unroll
        for (int i = 0; i < 4; i++) {
            float4 t = *(const float4*)&qp[i * 4];
            float x0 = t.x * scale, x1 = t.y * scale;
            float x2 = t.z * scale, x3 = t.w * scale;
            qn2 += x0 * x0 + x1 * x1 + x2 * x2 + x3 * x3;
            q2[2 * i]     = packf2(x0, x1);
            q2[2 * i + 1] = packf2(x2, x3);
        }
        qn2 += __shfl_xor_sync(0xFFFFFFFFu, qn2, 1, 4);
        qn2 += __shfl_xor_sync(0xFFFFFFFFu, qn2, 2, 4);
        const float m = sqrtf(qn2 * maxk2) + 1e-6f;   // Cauchy-Schwarz bound

        unsigned long long acc2[8];
#pragma unroll
        for (int i = 0; i < 8; i++) acc2[i] = 0ULL;
        float l = 0.0f;

        const int koff = lg * 16;
        for (int j = 0; j < NK_; j++) {
            const ulonglong2* kr2 = (const ulonglong2*)&Ks[j * DH_ + koff];
            unsigned long long sa = 0ULL, sb = 0ULL;
#pragma unroll
            for (int i = 0; i < 4; i++) {
                ulonglong2 t = kr2[i];
                sa = ffma2(q2[2 * i], t.x, sa);
                sb = ffma2(q2[2 * i + 1], t.y, sb);
            }
            float a0, a1, b0, b1;
            unpackf2(sa, a0, a1);
            unpackf2(sb, b0, b1);
            float s = (a0 + a1) + (b0 + b1);
            s += __shfl_xor_sync(0xFFFFFFFFu, s, 1, 4);
            s += __shfl_xor_sync(0xFFFFFFFFu, s, 2, 4);
            float p = __expf(s - m);
            l += p;
            unsigned long long p2 = packf2(p, p);
            const ulonglong2* vr2 = (const ulonglong2*)&Vs[j * DH_ + koff];
#pragma unroll
            for (int i = 0; i < 4; i++) {
                ulonglong2 t = vr2[i];
                acc2[2 * i]     = ffma2(p2, t.x, acc2[2 * i]);
                acc2[2 * i + 1] = ffma2(p2, t.y, acc2[2 * i + 1]);
            }
        }

        if (qgrp < NP_) {
            const float inv = 1.0f / l;
            __nv_bfloat16* base = A2 + ((size_t)b * NTOT + qtok) * KP + hoff + lg * 16;
#pragma unroll
            for (int i = 0; i < 4; i++) {
                float v0, v1, v2, v3;
                unpackf2(acc2[2 * i], v0, v1);
                unpackf2(acc2[2 * i + 1], v2, v3);
                v0 *= inv; v1 *= inv; v2 *= inv; v3 *= inv;
                __nv_bfloat16 h0, h1, h2, h3, l0, l1, l2, l3;
                split_bf16(v0, h0, l0); split_bf16(v1, h1, l1);
                split_bf16(v2, h2, l2); split_bf16(v3, h3, l3);
                uint2 hp = make_uint2(pack2(h0, h1), pack2(h2, h3));
                uint2 lp = make_uint2(pack2(l0, l1), pack2(l2, l3));
                *(uint2*)(base + i * 4)        = hp;
                *(uint2*)(base + 512 + i * 4)  = lp;
                *(uint2*)(base + 1024 + i * 4) = hp;
            }
        }
    } else {
        // ---------------- cls attention (25 warps) ----------------
        float* qs     = sh;                    // [64]
        float* sc     = sh + 64;               // [NTOT]
        float* redbuf = sh + 64 + NTOT;        // [25] (padded to 32)
        float* accs   = sh + 64 + NTOT + 32;   // [12][64]

        const int cb = blockIdx.x - 512;
        const int b = cb / H_;
        const int h = cb % H_;
        const int lane = tid & 31;
        const int warp = tid >> 5;             // 0..24
        const size_t bbase = (size_t)b * NTOT * QKVC;
        const int hoff = h * DH_;

        if (tid < DH_) qs[tid] = qkv[bbase + hoff + tid] * 0.125f;
        __syncthreads();

        float lmax = -1e30f;
        for (int j = tid; j < NTOT; j += ATT_T) {
            const float* kp = qkv + bbase + (size_t)j * QKVC + DIM_ + hoff;
            float s = 0.0f;
#pragma unroll
            for (int i = 0; i < 16; i++) {
                float4 kk = *(const float4*)&kp[i * 4];
                float4 qq = *(const float4*)&qs[i * 4];
                s += qq.x * kk.x + qq.y * kk.y + qq.z * kk.z + qq.w * kk.w;
            }
            sc[j] = s;
            lmax = fmaxf(lmax, s);
        }
#pragma unroll
        for (int o = 16; o; o >>= 1) lmax = fmaxf(lmax, __shfl_xor_sync(~0u, lmax, o));
        if (lane == 0) redbuf[warp] = lmax;
        __syncthreads();
        float m = -1e30f;
#pragma unroll
        for (int i = 0; i < 25; i++) m = fmaxf(m, redbuf[i]);
        __syncthreads();    // protect redbuf reuse

        float lsum = 0.0f;
        for (int j = tid; j < NTOT; j += ATT_T) {
            float p = __expf(sc[j] - m);
            sc[j] = p;
            lsum += p;
        }
#pragma unroll
        for (int o = 16; o; o >>= 1) lsum += __shfl_xor_sync(~0u, lsum, o);
        if (lane == 0) redbuf[warp] = lsum;
        __syncthreads();
        float l = 0.0f;
#pragma unroll
        for (int i = 0; i < 25; i++) l += redbuf[i];

        const int d = tid & 63;
        const int g = tid >> 6;      // 0..12
        float acc = 0.0f;
        if (g < 12) {
            for (int j = g; j < NTOT; j += 12)
                acc += sc[j] * qkv[bbase + (size_t)j * QKVC + 2 * DIM_ + hoff + d];
            accs[g * 64 + d] = acc;
        }
        __syncthreads();
        if (tid < DH_) {
            float o = 0.0f;
#pragma unroll
            for (int i = 0; i < 12; i++) o += accs[i * 64 + tid];
            o /= l;
            __nv_bfloat16 hh, ll;
            split_bf16(o, hh, ll);
            __nv_bfloat16* base = A2 + (size_t)b * NTOT * KP + hoff + tid;
            base[0]    = hh;
            base[512]  = ll;
            base[1024] = hh;
        }
    }
}

// ---------------------------------------------------------------------------
extern "C" void kernel_launch(void* const* d_in, const int* in_sizes, int n_in,
                              void* d_out, int out_size) {
    const float* x    = (const float*)d_in[0];
    const float* Wqkv = (const float*)d_in[1];
    const float* Wout = (const float*)d_in[2];
    const float* bout = (const float*)d_in[3];
    float* out = (float*)d_out;

    float* qkv = nullptr;
    __nv_bfloat16 *A2x = nullptr, *A2att = nullptr, *B2qkv = nullptr, *B2out = nullptr;
    cudaGetSymbolAddress((void**)&qkv, g_qkv);
    cudaGetSymbolAddress((void**)&A2x, g_A2x);
    cudaGetSymbolAddress((void**)&A2att, g_A2att);
    cudaGetSymbolAddress((void**)&B2qkv, g_B2qkv);
    cudaGetSymbolAddress((void**)&B2out, g_B2out);

    // gemm<2,3,2>: stage = 32KB, 3 stages = 96KB, 2 CTA/SM
    constexpr int SM_G1 = 3 * (128 * 128 + 128 * 128);
    // gemm<1,4,2>: stage = 24KB, 4 stages = 96KB, 2 CTA/SM
    constexpr int SM_G2 = 4 * (64 * 128 + 128 * 128);

    cudaFuncSetAttribute((const void*)&gemm_mma<2, 3, 2>,
                         cudaFuncAttributeMaxDynamicSharedMemorySize, SM_G1);
    cudaFuncSetAttribute((const void*)&gemm_mma<1, 4, 2>,
                         cudaFuncAttributeMaxDynamicSharedMemorySize, SM_G2);

    // conversions
    {
        size_t tot = (size_t)MROWS * 128;
        conv_x_kernel<<<(unsigned)((tot + 255) / 256), 256>>>(x, A2x);
        convW_kernel<<<dim3(QKVC / 32, DIM_ / 32), dim3(32, 32)>>>(Wqkv, B2qkv, QKVC);
        convW_kernel<<<dim3(DIM_ / 32, DIM_ / 32), dim3(32, 32)>>>(Wout, B2out, DIM_);
    }

    // 1) qkv = x @ W_qkv  (128x128 tiles, 1188 CTAs, 2 CTA/SM -> 4 even waves)
    gemm_mma<2, 3, 2><<<dim3(QKVC / 128, 99), 256, SM_G1>>>(
        A2x, B2qkv, nullptr, qkv, MROWS, QKVC);

    // 2) attention: 512 local blocks + 32 cls blocks, 800 threads each
    {
        int smem = 2 * NK_ * DH_ * (int)sizeof(float);   // 100864
        cudaFuncSetAttribute(attn_kernel,
                             cudaFuncAttributeMaxDynamicSharedMemorySize, smem);
        attn_kernel<<<B_ * H_ * F_ + B_ * H_, ATT_T, smem>>>(qkv, A2att);
    }

    // 3) out = att @ W_out + b_out  (64x128 tiles, 792 CTAs, 2 CTA/SM)
    gemm_mma<1, 4, 2><<<dim3(DIM_ / 128, 198), 256, SM_G2>>>(
        A2att, B2out, bout, out, MROWS, DIM_);
}

// round 16
// speedup vs baseline: 1.8436x; 1.8436x over previous
#include <cuda_runtime.h>
#include <cuda_bf16.h>
#include <cstdint>

// Problem constants
#define B_   4
#define F_   16
#define NP_  196
#define DIM_ 512
#define H_   8
#define DH_  64
#define NTOT 3137            // 1 + F*NP
#define MROWS (B_ * NTOT)    // 12548
#define MPAD  12800          // covers 99*128 and 198*64
#define QKVC (3 * H_ * DH_)  // 1536
#define NK_  197             // cls + 196 local keys
#define KP   1536            // split-bf16 K' = 3*512

// ---------------------------------------------------------------------------
// Scratch (allocation-free: __device__ globals)
// ---------------------------------------------------------------------------
__device__ float         g_qkv[(size_t)MROWS * QKVC];
__device__ __nv_bfloat16 g_A2x[(size_t)MPAD * KP];
__device__ __nv_bfloat16 g_A2att[(size_t)MPAD * KP];
__device__ __nv_bfloat16 g_B2qkv[(size_t)QKVC * KP];
__device__ __nv_bfloat16 g_B2out[(size_t)DIM_ * KP];

// ---------------------------------------------------------------------------
__device__ __forceinline__ uint32_t smem_to_u32(const void* p) {
    uint32_t a;
    asm("{ .reg .u64 t; cvta.to.shared.u64 t, %1; cvt.u32.u64 %0, t; }"
        : "=r"(a) : "l"(p));
    return a;
}

__device__ __forceinline__ void split_bf16(float v, __nv_bfloat16& h, __nv_bfloat16& l) {
    h = __float2bfloat16_rn(v);
    l = __float2bfloat16_rn(v - __bfloat162float(h));
}
__device__ __forceinline__ uint32_t pack2(__nv_bfloat16 a, __nv_bfloat16 b) {
    __nv_bfloat162 t = __halves2bfloat162(a, b);
    return *(uint32_t*)&t;
}

// packed f32x2 helpers (sm_100+)
__device__ __forceinline__ unsigned long long ffma2(unsigned long long a,
                                                    unsigned long long b,
                                                    unsigned long long c) {
    unsigned long long d;
    asm("fma.rn.f32x2 %0, %1, %2, %3;" : "=l"(d) : "l"(a), "l"(b), "l"(c));
    return d;
}
__device__ __forceinline__ unsigned long long packf2(float x, float y) {
    unsigned long long r;
    asm("mov.b64 %0, {%1, %2};" : "=l"(r) : "f"(x), "f"(y));
    return r;
}
__device__ __forceinline__ void unpackf2(unsigned long long r, float& x, float& y) {
    asm("mov.b64 {%0, %1}, %2;" : "=f"(x), "=f"(y) : "l"(r));
}

#define LDSM4(r, addr) \
    asm volatile("ldmatrix.sync.aligned.m8n8.x4.shared.b16 {%0,%1,%2,%3}, [%4];" \
                 : "=r"((r)[0]), "=r"((r)[1]), "=r"((r)[2]), "=r"((r)[3]) \
                 : "r"(addr))
#define CPA16(dst, src) \
    asm volatile("cp.async.cg.shared.global [%0], [%1], 16;" :: "r"(dst), "l"(src))

// ---------------------------------------------------------------------------
// HMMA GEMM: C[M,N] = A2[M,KP] . B2[N,KP]^T (+ bias).
// BK=64, 128B smem rows, seg^(row&7) swizzle -> conflict-free ldmatrix.
// MS = m16 subtiles per warp (2 -> 128x128 CTA, 1 -> 64x128),
// NSTG = stages, MINB = min blocks/SM. 8 warps 4(m)x2(n).
// ---------------------------------------------------------------------------
#define BK2 64
#define KIT2 (KP / BK2)            // 24

template <int MS, int NSTG, int MINB>
__global__ __launch_bounds__(256, MINB)
void gemm_mma(const __nv_bfloat16* __restrict__ A2,
              const __nv_bfloat16* __restrict__ B2,
              const float* __restrict__ bias,
              float* __restrict__ C, int M, int N) {
    constexpr int GBMt = MS * 64;
    constexpr int A_B  = GBMt * 128;
    constexpr int STG  = A_B + 128 * 128;
    extern __shared__ __align__(128) unsigned char smem[];

    const int tid  = threadIdx.x;
    const int wid  = tid >> 5;
    const int lane = tid & 31;
    const int wm = (wid & 3) * (MS * 16);
    const int wn = (wid >> 2) * 64;
    const int tm = blockIdx.y * GBMt;
    const int tn = blockIdx.x * 128;

    const uint32_t sbase = smem_to_u32(smem);

    const int row0 = tid >> 3;
    const int seg  = tid & 7;
    const __nv_bfloat16* gA0 = A2 + (size_t)(tm + row0) * KP + seg * 8;
    const __nv_bfloat16* gB0 = B2 + (size_t)(tn + row0) * KP + seg * 8;
    const uint32_t oA0 = row0 * 128 + ((seg ^ (row0 & 7)) * 16);
    const uint32_t oB0 = A_B + oA0;

    auto issue_stage = [&](int it) {
        if (it < KIT2) {
            int k0 = it * BK2;
            uint32_t bo = sbase + (it % NSTG) * STG;
#pragma unroll
            for (int t = 0; t < MS * 2; t++)
                CPA16(bo + oA0 + t * 4096, gA0 + (size_t)t * 32 * KP + k0);
#pragma unroll
            for (int t = 0; t < 4; t++)
                CPA16(bo + oB0 + t * 4096, gB0 + (size_t)t * 32 * KP + k0);
        }
        asm volatile("cp.async.commit_group;");
    };

    float acc[MS][8][4];
#pragma unroll
    for (int i = 0; i < MS; i++)
#pragma unroll
        for (int j = 0; j < 8; j++)
#pragma unroll
            for (int r = 0; r < 4; r++) acc[i][j][r] = 0.0f;

    const int rbase = lane & 15;
    const int kh = lane >> 4;

#pragma unroll
    for (int s = 0; s < NSTG - 1; s++) issue_stage(s);

    for (int it = 0; it < KIT2; ++it) {
        asm volatile("cp.async.wait_group %0;" :: "n"(NSTG - 2));
        __syncthreads();
        issue_stage(it + NSTG - 1);

        const uint32_t aB = sbase + (it % NSTG) * STG;
        const uint32_t bB = aB + A_B;

#pragma unroll
        for (int kk = 0; kk < 4; kk++) {
            const int segl = kk * 2 + kh;
            uint32_t a[MS][4];
#pragma unroll
            for (int i = 0; i < MS; i++) {
                int rA = wm + i * 16 + rbase;
                LDSM4(a[i], aB + rA * 128 + ((segl ^ (rA & 7)) * 16));
            }
            uint32_t b[4][4];
#pragma unroll
            for (int j2 = 0; j2 < 4; j2++) {
                int rB = wn + j2 * 16 + rbase;
                LDSM4(b[j2], bB + rB * 128 + ((segl ^ (rB & 7)) * 16));
            }
#pragma unroll
            for (int i = 0; i < MS; i++)
#pragma unroll
                for (int j = 0; j < 8; j++) {
                    uint32_t b0 = b[j >> 1][(j & 1)];
                    uint32_t b1 = b[j >> 1][(j & 1) + 2];
                    asm volatile(
                        "mma.sync.aligned.m16n8k16.row.col.f32.bf16.bf16.f32 "
                        "{%0,%1,%2,%3}, {%4,%5,%6,%7}, {%8,%9}, {%0,%1,%2,%3};"
                        : "+f"(acc[i][j][0]), "+f"(acc[i][j][1]),
                          "+f"(acc[i][j][2]), "+f"(acc[i][j][3])
                        : "r"(a[i][0]), "r"(a[i][1]), "r"(a[i][2]), "r"(a[i][3]),
                          "r"(b0), "r"(b1));
                }
        }
    }

#pragma unroll
    for (int i = 0; i < MS; i++) {
        int row0e = tm + wm + i * 16 + (lane >> 2);
#pragma unroll
        for (int half = 0; half < 2; half++) {
            int row = row0e + half * 8;
            if (row >= M) continue;
#pragma unroll
            for (int j = 0; j < 8; j++) {
                int col = tn + wn + j * 8 + (lane & 3) * 2;
                float2 v;
                v.x = acc[i][j][half * 2 + 0];
                v.y = acc[i][j][half * 2 + 1];
                if (bias) {
                    float2 bb = *(const float2*)(bias + col);
                    v.x += bb.x; v.y += bb.y;
                }
                *(float2*)(C + (size_t)row * N + col) = v;
            }
        }
    }
}

// ---------------------------------------------------------------------------
// conv_x: x fp32 [M,512] -> A2 split-bf16 [M,1536]  (hi | lo | hi)
// ---------------------------------------------------------------------------
__global__ __launch_bounds__(256)
void conv_x_kernel(const float* __restrict__ x, __nv_bfloat16* __restrict__ A2) {
    size_t i = (size_t)blockIdx.x * blockDim.x + threadIdx.x;
    if (i >= (size_t)MROWS * 128) return;
    size_t row = i >> 7;
    int c4 = (int)(i & 127);
    float4 v = *(const float4*)(x + row * 512 + c4 * 4);
    __nv_bfloat16 h0, h1, h2, h3, l0, l1, l2, l3;
    split_bf16(v.x, h0, l0); split_bf16(v.y, h1, l1);
    split_bf16(v.z, h2, l2); split_bf16(v.w, h3, l3);
    uint2 hp = make_uint2(pack2(h0, h1), pack2(h2, h3));
    uint2 lp = make_uint2(pack2(l0, l1), pack2(l2, l3));
    __nv_bfloat16* base = A2 + row * KP + c4 * 4;
    *(uint2*)(base)        = hp;
    *(uint2*)(base + 512)  = lp;
    *(uint2*)(base + 1024) = hp;
}

// ---------------------------------------------------------------------------
// convW: W fp32 [512,N] -> B2 split-bf16 [N,1536] (transposed, hi | hi | lo)
// ---------------------------------------------------------------------------
__global__ __launch_bounds__(1024)
void convW_kernel(const float* __restrict__ W, __nv_bfloat16* __restrict__ B2, int N) {
    __shared__ float t[32][33];
    int n0 = blockIdx.x * 32, k0 = blockIdx.y * 32;
    int tx = threadIdx.x, ty = threadIdx.y;
    t[ty][tx] = W[(size_t)(k0 + ty) * N + n0 + tx];
    __syncthreads();
    int n = n0 + ty, k = k0 + tx;
    float v = t[tx][ty];
    __nv_bfloat16 h, l;
    split_bf16(v, h, l);
    size_t base = (size_t)n * KP + k;
    B2[base]        = h;
    B2[base + 512]  = h;
    B2[base + 1024] = l;
}

// ---------------------------------------------------------------------------
// Merged attention (R14 configuration — thread-per-query, LDS.128 K/V reads,
// Cauchy-Schwarz bound as softmax max, packed f32x2 FMA).
// Blocks [0,512): local, [512,544): cls. Writes split-bf16 directly.
// ---------------------------------------------------------------------------
__global__ __launch_bounds__(256, 1)
void attn_kernel(const float* __restrict__ qkv, __nv_bfloat16* __restrict__ A2) {
    extern __shared__ float sh[];
    const int tid = threadIdx.x;

    if (blockIdx.x < 512) {
        float* Ks = sh;
        float* Vs = sh + NK_ * DH_;
        __shared__ int s_maxk2;

        const int blk = blockIdx.x;
        const int b = blk / (H_ * F_);
        const int rem = blk % (H_ * F_);
        const int h = rem / F_;
        const int fi = rem % F_;
        const int t0 = 1 + fi * NP_;

        const size_t bbase = (size_t)b * NTOT * QKVC;
        const int hoff = h * DH_;

        if (tid == 0) s_maxk2 = 0;
        for (int idx = tid; idx < NK_ * (DH_ / 4); idx += blockDim.x) {
            int j = idx >> 4;
            int d4 = idx & 15;
            int tok = (j == 0) ? 0 : (t0 + j - 1);
            const float* kp = qkv + bbase + (size_t)tok * QKVC + DIM_ + hoff + d4 * 4;
            *(float4*)&Ks[j * DH_ + d4 * 4] = *(const float4*)kp;
            *(float4*)&Vs[j * DH_ + d4 * 4] = *(const float4*)(kp + DIM_);
        }
        __syncthreads();

        if (tid < NK_) {
            float kn2 = 0.0f;
#pragma unroll
            for (int i = 0; i < 16; i++) {
                float4 kk = *(const float4*)&Ks[tid * DH_ + i * 4];
                kn2 += kk.x * kk.x + kk.y * kk.y + kk.z * kk.z + kk.w * kk.w;
            }
            atomicMax(&s_maxk2, __float_as_int(kn2));
        }
        __syncthreads();
        const float maxk2 = __int_as_float(s_maxk2);

        const int qi = tid;
        if (qi >= NP_) return;
        const int qtok = t0 + qi;
        const float scale = 0.125f;

        const float* qp = qkv + bbase + (size_t)qtok * QKVC + hoff;
        unsigned long long q2[32];
        float qn2 = 0.0f;
#pragma unroll
        for (int i = 0; i < 16; i++) {
            float4 t = *(const float4*)&qp[i * 4];
            float x0 = t.x * scale, x1 = t.y * scale;
            float x2 = t.z * scale, x3 = t.w * scale;
            qn2 += x0 * x0 + x1 * x1 + x2 * x2 + x3 * x3;
            q2[2 * i]     = packf2(x0, x1);
            q2[2 * i + 1] = packf2(x2, x3);
        }
        const float m = sqrtf(qn2 * maxk2) + 1e-6f;

        unsigned long long acc2[32];
#pragma unroll
        for (int i = 0; i < 32; i++) acc2[i] = 0ULL;
        float l = 0.0f;

        for (int j = 0; j < NK_; j++) {
            const ulonglong2* kr2 = (const ulonglong2*)&Ks[j * DH_];
            unsigned long long s2a = 0ULL, s2b = 0ULL, s2c = 0ULL, s2d = 0ULL;
#pragma unroll
            for (int i = 0; i < 16; i += 2) {
                ulonglong2 t0v = kr2[i];
                ulonglong2 t1v = kr2[i + 1];
                s2a = ffma2(q2[2 * i + 0], t0v.x, s2a);
                s2b = ffma2(q2[2 * i + 1], t0v.y, s2b);
                s2c = ffma2(q2[2 * i + 2], t1v.x, s2c);
                s2d = ffma2(q2[2 * i + 3], t1v.y, s2d);
            }
            float a0, a1, b0, b1, c0, c1, d0, d1;
            unpackf2(s2a, a0, a1); unpackf2(s2b, b0, b1);
            unpackf2(s2c, c0, c1); unpackf2(s2d, d0, d1);
            float s = ((a0 + a1) + (b0 + b1)) + ((c0 + c1) + (d0 + d1));
            float p = __expf(s - m);
            l += p;
            unsigned long long p2 = packf2(p, p);
            const ulonglong2* vr2 = (const ulonglong2*)&Vs[j * DH_];
#pragma unroll
            for (int i = 0; i < 16; i++) {
                ulonglong2 t = vr2[i];
                acc2[2 * i + 0] = ffma2(p2, t.x, acc2[2 * i + 0]);
                acc2[2 * i + 1] = ffma2(p2, t.y, acc2[2 * i + 1]);
            }
        }

        const float inv = 1.0f / l;
        __nv_bfloat16* base = A2 + ((size_t)b * NTOT + qtok) * KP + hoff;
#pragma unroll
        for (int i = 0; i < 16; i++) {
            float v0, v1, v2, v3;
            unpackf2(acc2[2 * i], v0, v1);
            unpackf2(acc2[2 * i + 1], v2, v3);
            v0 *= inv; v1 *= inv; v2 *= inv; v3 *= inv;
            __nv_bfloat16 h0, h1, h2, h3, l0, l1, l2, l3;
            split_bf16(v0, h0, l0); split_bf16(v1, h1, l1);
            split_bf16(v2, h2, l2); split_bf16(v3, h3, l3);
            uint2 hp = make_uint2(pack2(h0, h1), pack2(h2, h3));
            uint2 lp = make_uint2(pack2(l0, l1), pack2(l2, l3));
            *(uint2*)(base + i * 4)        = hp;
            *(uint2*)(base + 512 + i * 4)  = lp;
            *(uint2*)(base + 1024 + i * 4) = hp;
        }
    } else {
        float* qs     = sh;
        float* sc     = sh + 64;
        float* redbuf = sh + 64 + NTOT;
        float* accs   = sh + 64 + NTOT + 8;

        const int cb = blockIdx.x - 512;
        const int b = cb / H_;
        const int h = cb % H_;
        const int lane = tid & 31;
        const int warp = tid >> 5;
        const size_t bbase = (size_t)b * NTOT * QKVC;
        const int hoff = h * DH_;

        if (tid < DH_) qs[tid] = qkv[bbase + hoff + tid] * 0.125f;
        __syncthreads();

        float lmax = -1e30f;
        for (int j = tid; j < NTOT; j += 256) {
            const float* kp = qkv + bbase + (size_t)j * QKVC + DIM_ + hoff;
            float s = 0.0f;
#pragma unroll
            for (int i = 0; i < 16; i++) {
                float4 kk = *(const float4*)&kp[i * 4];
                float4 qq = *(const float4*)&qs[i * 4];
                s += qq.x * kk.x + qq.y * kk.y + qq.z * kk.z + qq.w * kk.w;
            }
            sc[j] = s;
            lmax = fmaxf(lmax, s);
        }
#pragma unroll
        for (int o = 16; o; o >>= 1) lmax = fmaxf(lmax, __shfl_xor_sync(~0u, lmax, o));
        if (lane == 0) redbuf[warp] = lmax;
        __syncthreads();
        float m = fmaxf(fmaxf(fmaxf(redbuf[0], redbuf[1]), fmaxf(redbuf[2], redbuf[3])),
                        fmaxf(fmaxf(redbuf[4], redbuf[5]), fmaxf(redbuf[6], redbuf[7])));
        __syncthreads();

        float lsum = 0.0f;
        for (int j = tid; j < NTOT; j += 256) {
            float p = __expf(sc[j] - m);
            sc[j] = p;
            lsum += p;
        }
#pragma unroll
        for (int o = 16; o; o >>= 1) lsum += __shfl_xor_sync(~0u, lsum, o);
        if (lane == 0) redbuf[warp] = lsum;
        __syncthreads();
        float l = redbuf[0] + redbuf[1] + redbuf[2] + redbuf[3] +
                  redbuf[4] + redbuf[5] + redbuf[6] + redbuf[7];

        const int d = tid & 63;
        const int g = tid >> 6;
        float acc = 0.0f;
        for (int j = g; j < NTOT; j += 4)
            acc += sc[j] * qkv[bbase + (size_t)j * QKVC + 2 * DIM_ + hoff + d];
        accs[g * 64 + d] = acc;
        __syncthreads();
        if (tid < DH_) {
            float o = (accs[0 * 64 + tid] + accs[1 * 64 + tid] +
                       accs[2 * 64 + tid] + accs[3 * 64 + tid]) / l;
            __nv_bfloat16 hh, ll;
            split_bf16(o, hh, ll);
            __nv_bfloat16* base = A2 + (size_t)b * NTOT * KP + hoff + tid;
            base[0]    = hh;
            base[512]  = ll;
            base[1024] = hh;
        }
    }
}

// ---------------------------------------------------------------------------
extern "C" void kernel_launch(void* const* d_in, const int* in_sizes, int n_in,
                              void* d_out, int out_size) {
    const float* x    = (const float*)d_in[0];
    const float* Wqkv = (const float*)d_in[1];
    const float* Wout = (const float*)d_in[2];
    const float* bout = (const float*)d_in[3];
    float* out = (float*)d_out;

    float* qkv = nullptr;
    __nv_bfloat16 *A2x = nullptr, *A2att = nullptr, *B2qkv = nullptr, *B2out = nullptr;
    cudaGetSymbolAddress((void**)&qkv, g_qkv);
    cudaGetSymbolAddress((void**)&A2x, g_A2x);
    cudaGetSymbolAddress((void**)&A2att, g_A2att);
    cudaGetSymbolAddress((void**)&B2qkv, g_B2qkv);
    cudaGetSymbolAddress((void**)&B2out, g_B2out);

    // gemm<2,3,2>: stage = 32KB, 3 stages = 96KB, 2 CTA/SM
    constexpr int SM_G1 = 3 * (128 * 128 + 128 * 128);
    // gemm<1,4,2>: stage = 24KB, 4 stages = 96KB, 2 CTA/SM
    constexpr int SM_G2 = 4 * (64 * 128 + 128 * 128);

    cudaFuncSetAttribute((const void*)&gemm_mma<2, 3, 2>,
                         cudaFuncAttributeMaxDynamicSharedMemorySize, SM_G1);
    cudaFuncSetAttribute((const void*)&gemm_mma<1, 4, 2>,
                         cudaFuncAttributeMaxDynamicSharedMemorySize, SM_G2);

    // conversions
    {
        size_t tot = (size_t)MROWS * 128;
        conv_x_kernel<<<(unsigned)((tot + 255) / 256), 256>>>(x, A2x);
        convW_kernel<<<dim3(QKVC / 32, DIM_ / 32), dim3(32, 32)>>>(Wqkv, B2qkv, QKVC);
        convW_kernel<<<dim3(DIM_ / 32, DIM_ / 32), dim3(32, 32)>>>(Wout, B2out, DIM_);
    }

    // 1) qkv = x @ W_qkv  (128x128 tiles, 1188 CTAs, 2 CTA/SM -> 4 even waves)
    gemm_mma<2, 3, 2><<<dim3(QKVC / 128, 99), 256, SM_G1>>>(
        A2x, B2qkv, nullptr, qkv, MROWS, QKVC);

    // 2) attention: 512 local blocks + 32 cls blocks, 256 threads
    {
        int smem = 2 * NK_ * DH_ * (int)sizeof(float);   // 100864
        cudaFuncSetAttribute(attn_kernel,
                             cudaFuncAttributeMaxDynamicSharedMemorySize, smem);
        attn_kernel<<<B_ * H_ * F_ + B_ * H_, 256, smem>>>(qkv, A2att);
    }

    // 3) out = att @ W_out + b_out  (64x128 tiles, 792 CTAs, 2 CTA/SM)
    gemm_mma<1, 4, 2><<<dim3(DIM_ / 128, 198), 256, SM_G2>>>(
        A2att, B2out, bout, out, MROWS, DIM_);
}